// round 13
// baseline (speedup 1.0000x reference)
#include <cuda_runtime.h>
#include <cuda_bf16.h>
#include <cstdint>

// KinematicWaveRouting via the scalar transfer function of the 20-segment chain.
//   y_t = y_{t-1} + u_t - sum_{j=0..7} c_j u_{t-20-j},   u = runoff * basin * 50
//   8-tap NegBinomial kernel, two-moment matched (rel err ~1.8e-4, thresh 1e-3).
// R13: one warp owns a CONTIGUOUS ROW PAIR (rows 2w, 2w+1) = 8192 floats =
// 32 chunks of 256 steps, single base pointer (no dual-pointer ALU).
// Chunks 0 and 16 are row starts: warm inputs forced to zero.
// Per-lane scale (row0 for lanes 0-15, row1 for lanes 16-31).
// Tile/pipeline identical to R11: chunk-major 144B rows, 16B cp.async,
// LDS.128 loads, STS.128 in-place outputs, LDS.128+STG.128 drain.

#define T_LEN    4096
#define CHUNK    256
#define NCHUNK   32
#define RPB      4          // warps per block -> 8 rows per block
#define NTAPS    8
#define TSTRIDE  36         // floats per tile row (144 bytes)

// -c'_m, m = 20..27 (two-moment matched)
static __device__ constexpr float CNEG[NTAPS] = {
    -0.12252114f, -0.24315331f, -0.25531098f, -0.18722805f,
    -0.10362058f, -0.05167495f, -0.02153122f, -0.01495978f
};
// warm-start weights g'_m = 1 - cumsum(c'), lags 20..26 (g'_27 = 0)
static __device__ constexpr float GW[7] = {
    0.87747886f, 0.63432555f, 0.37901458f, 0.19178653f,
    0.08816595f, 0.03649100f, 0.01495978f
};

__device__ __forceinline__ void cpasync16(uint32_t s, const float* g) {
    asm volatile("cp.async.cg.shared.global [%0], [%1], 16;" :: "r"(s), "l"(g) : "memory");
}
__device__ __forceinline__ void cpcommit() {
    asm volatile("cp.async.commit_group;" ::: "memory");
}
template <int N>
__device__ __forceinline__ void cpwait() {
    asm volatile("cp.async.wait_group %0;" :: "n"(N) : "memory");
}
__device__ __forceinline__ void sts128(uint32_t a, float v0, float v1, float v2, float v3) {
    asm volatile("st.shared.v4.f32 [%0], {%1, %2, %3, %4};"
                 :: "r"(a), "f"(v0), "f"(v1), "f"(v2), "f"(v3) : "memory");
}

// Prefetch group GIDX (1..8): 8 x 16B cp.async per lane; instruction i covers
// chunks 4i+p at quad q. rq = series_base + p*CHUNK + q*4 - 32.
#define PREFETCH(TU, GIDX)                                                  \
    do {                                                                    \
        const float* rg_ = rq + (GIDX) * 32;                                \
        _Pragma("unroll")                                                   \
        for (int i = 0; i < 8; i++)                                         \
            cpasync16((TU) + i * 576, rg_ + i * 1024);                      \
        cpcommit();                                                         \
    } while (0)

// Load the lane's 32 inputs (own chunk row = lane): 8 x LDS.128.
#define LOAD_W(W, TB)                                                       \
    do {                                                                    \
        const float4* r4 = (const float4*)((TB) + lane * TSTRIDE);          \
        _Pragma("unroll")                                                   \
        for (int k = 0; k < 8; k++) {                                       \
            float4 t = r4[k];                                               \
            W[4 * k] = t.x; W[4 * k + 1] = t.y;                             \
            W[4 * k + 2] = t.z; W[4 * k + 3] = t.w;                         \
        }                                                                   \
    } while (0)

// 32 steps as 8 quads; scaled outputs overwrite the lane's own row in place.
#define GROUP_BODY(PREV, CUR, TROWU)                                        \
    do {                                                                    \
        _Pragma("unroll")                                                   \
        for (int qq = 0; qq < 8; qq++) {                                    \
            float vv[4];                                                    \
            _Pragma("unroll")                                               \
            for (int s = 0; s < 4; s++) {                                   \
                const int m = 4 * qq + s;                                   \
                float acc = CUR[m];                                         \
                _Pragma("unroll")                                           \
                for (int j = 0; j < NTAPS; j++) {                           \
                    const int k = m - (20 + j);                             \
                    float w = (k >= 0) ? CUR[k] : PREV[32 + k];             \
                    acc = fmaf(CNEG[j], w, acc);                            \
                }                                                           \
                y += acc;                                                   \
                vv[s] = y * scale;                                          \
            }                                                               \
            sts128((TROWU) + qq * 16, vv[0], vv[1], vv[2], vv[3]);          \
        }                                                                   \
    } while (0)

// Drain group GIDX: lane handles (chunk = 4k+p, quad = q): LDS.128 from the
// chunk-major tile, STG.128 covering fully-written 128B lines.
#define DRAIN(TB, GIDX)                                                     \
    do {                                                                    \
        const float* sp = (TB) + p * TSTRIDE + q * 4;                       \
        float* gp = odrain + ((GIDX) - 1) * 32;                             \
        _Pragma("unroll")                                                   \
        for (int k = 0; k < 8; k++) {                                       \
            float4 v = *(const float4*)(sp + k * 4 * TSTRIDE);              \
            *(float4*)(gp + k * 1024) = v;                                  \
        }                                                                   \
    } while (0)

__global__ __launch_bounds__(128, 6)
void kinematic_wave_kernel(const float* __restrict__ runoff,
                           const float* __restrict__ basin,
                           float* __restrict__ out,
                           int B)
{
    __shared__ __align__(16) float tile[2][RPB][NCHUNK * TSTRIDE];

    const int warp = threadIdx.x >> 5;
    const int lane = threadIdx.x & 31;
    const int pair = blockIdx.x * RPB + warp;      // row pair index
    const int row0 = pair * 2;
    if (row0 >= B) return;

    const int p = lane >> 3;
    const int q = lane & 7;

    float* X = &tile[0][warp][0];
    float* Y = &tile[1][warp][0];
    const uint32_t lslot = (uint32_t)(p * 144 + q * 16);
    const uint32_t Xu = (uint32_t)__cvta_generic_to_shared(X) + lslot;
    const uint32_t Yu = (uint32_t)__cvta_generic_to_shared(Y) + lslot;
    const uint32_t Xrow = (uint32_t)__cvta_generic_to_shared(X) + lane * 144;
    const uint32_t Yrow = (uint32_t)__cvta_generic_to_shared(Y) + lane * 144;

    // lanes 0-15 -> row0 (chunks 0..15), lanes 16-31 -> row0+1 (chunks 16..31)
    const float scale = basin[row0 + (lane >> 4)] * 50.0f;
    const float* __restrict__ rq =
        runoff + (size_t)row0 * T_LEN + p * CHUNK + q * 4 - 32;
    float* __restrict__ odrain =
        out + (size_t)row0 * T_LEN + p * CHUNK + q * 4;

    float W0[32], W1[32], y;

    // ---- warm fill -> X; chunks 0 and 16 (row starts) are all t<0 -> zeros ----
    X[lane] = 0.0f;                  // chunk-0 row (floats 0..31 of row 0)
    X[16 * TSTRIDE + lane] = 0.0f;   // chunk-16 row
#pragma unroll
    for (int i = 0; i < 8; i++) {
        if (i == 0 || i == 4) {      // chunks 4i+p: p==0 is a row start
            if (p != 0) cpasync16(Xu + i * 576, rq + i * 1024);
        } else {
            cpasync16(Xu + i * 576, rq + i * 1024);
        }
    }
    cpcommit();
    PREFETCH(Yu, 1);                                  // group 1 in flight
    cpwait<1>(); __syncwarp();                        // warm batch landed
    LOAD_W(W0, X);
    // warm FIR: W0[j] = u(t0-32+j), lag = 31-j; y = outlet at t0-1 (unscaled)
    {
        float s = 0.0f;
#pragma unroll
        for (int j = 12; j < 32; j++) s += W0[j];                 // lags 0..19
        float s2 = 0.0f;
#pragma unroll
        for (int j = 5; j < 12; j++) s2 = fmaf(GW[11 - j], W0[j], s2); // 20..26
        y = s + s2;
    }
    __syncwarp();                                     // X fully consumed

    // ---- 8 main groups of 32 steps (4 x pair loop, runtime GIDX) ----
#pragma unroll 1
    for (int gg = 0; gg < 4; gg++) {
        const int g1 = 2 * gg + 1;
        // group g1: inputs in Y; prefetch g1+1 -> X
        PREFETCH(Xu, g1 + 1);
        cpwait<1>(); __syncwarp();
        LOAD_W(W1, Y);
        GROUP_BODY(W0, W1, Yrow);
        __syncwarp();
        DRAIN(Y, g1);
        __syncwarp();

        const int g2 = 2 * gg + 2;
        // group g2: inputs in X; prefetch g2+1 -> Y (except after last)
        if (gg < 3) {
            PREFETCH(Yu, g2 + 1);
            cpwait<1>();
        } else {
            cpwait<0>();
        }
        __syncwarp();
        LOAD_W(W0, X);
        GROUP_BODY(W1, W0, Xrow);
        __syncwarp();
        DRAIN(X, g2);
        __syncwarp();
    }
}

extern "C" void kernel_launch(void* const* d_in, const int* in_sizes, int n_in,
                              void* d_out, int out_size)
{
    const float* runoff = (const float*)d_in[0];   // (B, T) float32
    const float* basin  = (const float*)d_in[1];   // (B, 1) float32
    float* out = (float*)d_out;                    // (B, T) float32

    int B = in_sizes[1];                           // 8192
    int pairs = B / 2;                             // 4096
    int blocks = (pairs + RPB - 1) / RPB;          // 1024
    kinematic_wave_kernel<<<blocks, 128>>>(runoff, basin, out, B);
}

// round 14
// speedup vs baseline: 1.2597x; 1.2597x over previous
#include <cuda_runtime.h>
#include <cuda_bf16.h>
#include <cstdint>

// KinematicWaveRouting via the scalar transfer function of the 20-segment chain.
//   y_t = y_{t-1} + u_t - sum_{j=0..7} c_j u_{t-20-j},   u = runoff * basin * 50
//   8-tap NegBinomial kernel, two-moment matched (rel err ~1.8e-4, thresh 1e-3).
// One warp per row, lane = 128-step chunk, warm-started 32 steps early.
// Inputs: 16B cp.async (.cg) into chunk-major tile (stride 144B), double-buffered.
// Body: 4-step quads -> y*scale -> STS.128 in place (chunk-major).
// Drain: 8 LDS.128 + 8 STG.128 with .cs streaming hint (outputs never re-read;
// keeps L2 for the input stream's halo re-reads).
// All smem phases conflict-free. (= R11 + st.global.cs)

#define T_LEN    4096
#define CHUNK    128
#define NCHUNK   32
#define RPB      4
#define NTAPS    8
#define TSTRIDE  36          // floats per tile row (144 bytes)

// -c'_m, m = 20..27 (two-moment matched)
static __device__ constexpr float CNEG[NTAPS] = {
    -0.12252114f, -0.24315331f, -0.25531098f, -0.18722805f,
    -0.10362058f, -0.05167495f, -0.02153122f, -0.01495978f
};
// warm-start weights g'_m = 1 - cumsum(c'), lags 20..26 (g'_27 = 0)
static __device__ constexpr float GW[7] = {
    0.87747886f, 0.63432555f, 0.37901458f, 0.19178653f,
    0.08816595f, 0.03649100f, 0.01495978f
};

__device__ __forceinline__ void cpasync16(uint32_t s, const float* g) {
    asm volatile("cp.async.cg.shared.global [%0], [%1], 16;" :: "r"(s), "l"(g) : "memory");
}
__device__ __forceinline__ void cpcommit() {
    asm volatile("cp.async.commit_group;" ::: "memory");
}
template <int N>
__device__ __forceinline__ void cpwait() {
    asm volatile("cp.async.wait_group %0;" :: "n"(N) : "memory");
}
__device__ __forceinline__ void sts128(uint32_t a, float v0, float v1, float v2, float v3) {
    asm volatile("st.shared.v4.f32 [%0], {%1, %2, %3, %4};"
                 :: "r"(a), "f"(v0), "f"(v1), "f"(v2), "f"(v3) : "memory");
}
__device__ __forceinline__ void stg128cs(float* p, float4 v) {
    asm volatile("st.global.cs.v4.f32 [%0], {%1, %2, %3, %4};"
                 :: "l"(p), "f"(v.x), "f"(v.y), "f"(v.z), "f"(v.w) : "memory");
}

// Prefetch group GIDX: 8 x 16B cp.async per lane; instruction i covers chunks
// 4i..4i+3. rq = rrow + (lane>>3)*CHUNK + (lane&7)*4 - 32.
#define PREFETCH(TU, GIDX)                                                  \
    do {                                                                    \
        _Pragma("unroll")                                                   \
        for (int i = 0; i < 8; i++)                                         \
            cpasync16((TU) + i * 576, rq + i * 512 + (GIDX) * 32);          \
        cpcommit();                                                         \
    } while (0)

// Load the lane's 32 inputs (own chunk row): 8 x LDS.128, conflict-free.
#define LOAD_W(W, TB)                                                       \
    do {                                                                    \
        const float4* r4 = (const float4*)((TB) + lane * TSTRIDE);          \
        _Pragma("unroll")                                                   \
        for (int k = 0; k < 8; k++) {                                       \
            float4 t = r4[k];                                               \
            W[4 * k] = t.x; W[4 * k + 1] = t.y;                             \
            W[4 * k + 2] = t.z; W[4 * k + 3] = t.w;                         \
        }                                                                   \
    } while (0)

// 32 steps as 8 quads; scaled outputs overwrite the lane's own row
// (chunk-major) via STS.128.  TROWU = u32 smem addr of the lane's row.
#define GROUP_BODY(PREV, CUR, TROWU)                                        \
    do {                                                                    \
        _Pragma("unroll")                                                   \
        for (int qq = 0; qq < 8; qq++) {                                    \
            float vv[4];                                                    \
            _Pragma("unroll")                                               \
            for (int s = 0; s < 4; s++) {                                   \
                const int m = 4 * qq + s;                                   \
                float acc = CUR[m];                                         \
                _Pragma("unroll")                                           \
                for (int j = 0; j < NTAPS; j++) {                           \
                    const int k = m - (20 + j);                             \
                    float w = (k >= 0) ? CUR[k] : PREV[32 + k];             \
                    acc = fmaf(CNEG[j], w, acc);                            \
                }                                                           \
                y += acc;                                                   \
                vv[s] = y * scale;                                          \
            }                                                               \
            sts128((TROWU) + qq * 16, vv[0], vv[1], vv[2], vv[3]);          \
        }                                                                   \
    } while (0)

// Drain group GIDX: lane handles (chunk = 4k + (lane>>3), quad = lane&7):
// LDS.128 from the chunk-major tile, STG.128.cs covering full 128B lines.
#define DRAIN(TB, GIDX)                                                     \
    do {                                                                    \
        const float* sp = (TB) + (lane >> 3) * TSTRIDE + (lane & 7) * 4;    \
        float* gp = odrain + ((GIDX) - 1) * 32;                             \
        _Pragma("unroll")                                                   \
        for (int k = 0; k < 8; k++) {                                       \
            float4 v = *(const float4*)(sp + k * 4 * TSTRIDE);              \
            stg128cs(gp + k * 512, v);                                      \
        }                                                                   \
    } while (0)

__global__ __launch_bounds__(128, 6)
void kinematic_wave_kernel(const float* __restrict__ runoff,
                           const float* __restrict__ basin,
                           float* __restrict__ out,
                           int B)
{
    __shared__ __align__(16) float tile[2][RPB][NCHUNK * TSTRIDE];

    const int warp = threadIdx.x >> 5;
    const int lane = threadIdx.x & 31;
    const int row  = blockIdx.x * RPB + warp;
    if (row >= B) return;

    float* X = &tile[0][warp][0];
    float* Y = &tile[1][warp][0];
    const uint32_t lslot = (uint32_t)((lane >> 3) * 144 + (lane & 7) * 16);
    const uint32_t Xu = (uint32_t)__cvta_generic_to_shared(X) + lslot;
    const uint32_t Yu = (uint32_t)__cvta_generic_to_shared(Y) + lslot;
    const uint32_t Xrow = (uint32_t)__cvta_generic_to_shared(X) + lane * 144;
    const uint32_t Yrow = (uint32_t)__cvta_generic_to_shared(Y) + lane * 144;

    const float scale = basin[row] * 50.0f;
    const float* __restrict__ rq =
        runoff + (size_t)row * T_LEN + (lane >> 3) * CHUNK + (lane & 7) * 4 - 32;
    float* __restrict__ odrain =
        out + (size_t)row * T_LEN + (lane >> 3) * CHUNK + (lane & 7) * 4;

    float W0[32], W1[32], y;

    // ---- warm fill -> X (chunk 0 is all t<0 -> zeros) ----
    X[lane] = 0.0f;                                   // chunk-0 row, float = lane
#pragma unroll
    for (int i = 0; i < 8; i++) {
        if (i == 0) { if ((lane >> 3) != 0) cpasync16(Xu, rq); }
        else cpasync16(Xu + i * 576, rq + i * 512);
    }
    cpcommit();
    PREFETCH(Yu, 1);                                  // group 1 in flight
    cpwait<1>(); __syncwarp();                        // warm batch landed
    LOAD_W(W0, X);
    // warm FIR: W0[j] = u(t0-32+j), lag = 31-j; y = outlet at t0-1 (unscaled)
    {
        float s = 0.0f;
#pragma unroll
        for (int j = 12; j < 32; j++) s += W0[j];                 // lags 0..19
        float s2 = 0.0f;
#pragma unroll
        for (int j = 5; j < 12; j++) s2 = fmaf(GW[11 - j], W0[j], s2); // 20..26
        y = s + s2;
    }
    __syncwarp();                                     // X fully consumed

    // ---- group 1: inputs in Y; prefetch G2 -> X ----
    PREFETCH(Xu, 2);
    cpwait<1>(); __syncwarp();
    LOAD_W(W1, Y);
    GROUP_BODY(W0, W1, Yrow);
    __syncwarp();
    DRAIN(Y, 1);
    __syncwarp();

    // ---- group 2: inputs in X; prefetch G3 -> Y ----
    PREFETCH(Yu, 3);
    cpwait<1>(); __syncwarp();
    LOAD_W(W0, X);
    GROUP_BODY(W1, W0, Xrow);
    __syncwarp();
    DRAIN(X, 2);
    __syncwarp();

    // ---- group 3: inputs in Y; prefetch G4 -> X ----
    PREFETCH(Xu, 4);
    cpwait<1>(); __syncwarp();
    LOAD_W(W1, Y);
    GROUP_BODY(W0, W1, Yrow);
    __syncwarp();
    DRAIN(Y, 3);
    __syncwarp();

    // ---- group 4: inputs in X ----
    cpwait<0>(); __syncwarp();
    LOAD_W(W0, X);
    GROUP_BODY(W1, W0, Xrow);
    __syncwarp();
    DRAIN(X, 4);
}

extern "C" void kernel_launch(void* const* d_in, const int* in_sizes, int n_in,
                              void* d_out, int out_size)
{
    const float* runoff = (const float*)d_in[0];   // (B, T) float32
    const float* basin  = (const float*)d_in[1];   // (B, 1) float32
    float* out = (float*)d_out;                    // (B, T) float32

    int B = in_sizes[1];                           // 8192
    int blocks = (B + RPB - 1) / RPB;              // 2048
    kinematic_wave_kernel<<<blocks, 128>>>(runoff, basin, out, B);
}